// round 16
// baseline (speedup 1.0000x reference)
#include <cuda_runtime.h>
#include <cuda_bf16.h>
#include <math.h>
#include <stdint.h>

#define MSAMP 16384

// tcgen05 is only encodable on arch-specific / family-specific Blackwell targets.
// A plain compute_103 pass (no 'a' suffix) gets a SIMT fallback body instead.
#if !defined(__CUDA_ARCH__) || defined(__CUDA_ARCH_FEAT_SM103_ALL) || \
    defined(__CUDA_ARCH_FEAT_SM100_ALL) || defined(__CUDA_ARCH_FEAT_SM101_ALL) || \
    (defined(__CUDA_ARCH_FAMILY_SPECIFIC__) && (__CUDA_ARCH_FAMILY_SPECIFIC__ >= 1000))
#define HAS_TC 1
#else
#define HAS_TC 0
#endif

// ---------------- scratch (device globals; no runtime allocation) ----------------
__device__ float g_H1p[MSAMP * 512];
__device__ float g_H2p[MSAMP * 512];
__device__ float g_H1r[3 * MSAMP * 256];
__device__ float g_H2r[3 * MSAMP * 256];
__device__ float g_G1p[MSAMP * 3 * 512];
__device__ float g_G1r[3 * MSAMP * 2 * 256];
__device__ float g_aux[MSAMP * 9];

__device__ __nv_bfloat16 g_H1ph[MSAMP * 512],       g_H1pl[MSAMP * 512];
__device__ __nv_bfloat16 g_H1rh[3 * MSAMP * 256],   g_H1rl[3 * MSAMP * 256];
__device__ __nv_bfloat16 g_Aph [MSAMP * 3 * 512],   g_Apl [MSAMP * 3 * 512];
__device__ __nv_bfloat16 g_Arh [3 * MSAMP * 2 * 256], g_Arl[3 * MSAMP * 2 * 256];
__device__ __nv_bfloat16 g_W1d_h[512 * 512], g_W1d_l[512 * 512];   // W1 direct  [j][i]
__device__ __nv_bfloat16 g_W1t_h[512 * 512], g_W1t_l[512 * 512];   // W1 transp  [n][k]
__device__ __nv_bfloat16 g_Wrd_h[3 * 256 * 256], g_Wrd_l[3 * 256 * 256];
__device__ __nv_bfloat16 g_Wrt_h[3 * 256 * 256], g_Wrt_l[3 * 256 * 256];

__device__ __forceinline__ float sigf(float z) { return 1.0f / (1.0f + expf(-z)); }

__device__ __forceinline__ float wred(float v) {
#pragma unroll
    for (int o = 16; o; o >>= 1) v += __shfl_xor_sync(0xffffffffu, v, o);
    return v;
}

__device__ __forceinline__ void split_bf16(float v, __nv_bfloat16& h, __nv_bfloat16& l) {
    h = __float2bfloat16(v);
    l = __float2bfloat16(v - __bfloat162float(h));
}

__device__ __forceinline__ uint32_t pack_bf(__nv_bfloat16 a, __nv_bfloat16 b) {
    return (uint32_t)__bfloat16_as_ushort(a) | ((uint32_t)__bfloat16_as_ushort(b) << 16);
}

// two packed bf16 (hi word / lo word of u) + their lo-correction -> two fp32
__device__ __forceinline__ void cvt2(uint32_t h, uint32_t l, float& f0, float& f1) {
    f0 = __uint_as_float(h << 16)         + __uint_as_float(l << 16);
    f1 = __uint_as_float(h & 0xffff0000u) + __uint_as_float(l & 0xffff0000u);
}

// ---------------- PTX helpers (sm_103a tcgen05) ----------------
__device__ __forceinline__ uint32_t smem_u32(const void* p) {
    uint32_t a;
    asm("{ .reg .u64 t; cvta.to.shared.u64 t, %1; cvt.u32.u64 %0, t; }" : "=r"(a) : "l"(p));
    return a;
}
#define MBAR_INIT(addr, cnt) \
    asm volatile("mbarrier.init.shared.b64 [%0], %1;" :: "r"(addr), "r"((uint32_t)(cnt)) : "memory")
#define MBAR_WAIT(addr, par) do {                                                            \
    uint32_t _m = (addr), _p = (uint32_t)(par), _d;                                          \
    asm volatile("{\n\t.reg .pred p;\n\t"                                                    \
        "mbarrier.try_wait.parity.acquire.cta.shared::cta.b64 p, [%1], %2;\n\t"              \
        "selp.b32 %0,1,0,p;\n\t}" : "=r"(_d) : "r"(_m), "r"(_p) : "memory");                 \
    while (!_d) {                                                                            \
        asm volatile("{\n\t.reg .pred p;\n\t"                                                \
            "mbarrier.try_wait.parity.acquire.cta.shared::cta.b64 p, [%1], %2, 0x989680;\n\t"\
            "selp.b32 %0,1,0,p;\n\t}" : "=r"(_d) : "r"(_m), "r"(_p) : "memory");             \
    }                                                                                        \
} while (0)

#if HAS_TC
__device__ __forceinline__ uint32_t elect1() {
    uint32_t p;
    asm volatile("{\n\t.reg .pred p;\n\telect.sync _|p, 0xFFFFFFFF;\n\tselp.b32 %0,1,0,p;\n\t}" : "=r"(p));
    return p;
}
__device__ __forceinline__ uint64_t sdesc(uint32_t addr) {
    return ((uint64_t)2 << 61) | ((uint64_t)1 << 46) | ((uint64_t)64 << 32) |
           ((uint64_t)1 << 16) | ((addr >> 4) & 0x3FFF);
}
__device__ __forceinline__ void mma_f16_ss(uint32_t d, uint64_t ad, uint64_t bd,
                                           uint32_t idesc, uint32_t en) {
    asm volatile(
        "{\n\t.reg .pred p;\n\tsetp.ne.u32 p, %5, 0;\n\t"
        "tcgen05.mma.cta_group::1.kind::f16 [%0], %1, %2, %3, {%4,%4,%4,%4}, p;\n\t}"
        :: "r"(d), "l"(ad), "l"(bd), "r"(idesc), "r"(0u), "r"(en) : "memory");
}
#define TCG_ALLOC(smem_addr, n) \
    asm volatile("tcgen05.alloc.cta_group::1.sync.aligned.shared::cta.b32 [%0], %1;" \
                 :: "r"(smem_addr), "r"((uint32_t)(n)) : "memory")
#define TCG_RELINQ() \
    asm volatile("tcgen05.relinquish_alloc_permit.cta_group::1.sync.aligned;")
#define TCG_DEALLOC(t, n) \
    asm volatile("tcgen05.dealloc.cta_group::1.sync.aligned.b32 %0, %1;" :: "r"(t), "r"((uint32_t)(n)))
#define TCG_COMMIT(bar) \
    asm volatile("tcgen05.commit.cta_group::1.mbarrier::arrive::one.shared::cluster.b64 [%0];" \
                 :: "r"(bar) : "memory")
#define TCG_FENCE_AFTER() asm volatile("tcgen05.fence::after_thread_sync;" ::: "memory")
#define TCG_WAIT_LD()     asm volatile("tcgen05.wait::ld.sync.aligned;" ::: "memory")
#define TCG_LD32(r, addr) \
    asm volatile("tcgen05.ld.sync.aligned.32x32b.x32.b32 " \
        "{%0, %1, %2, %3, %4, %5, %6, %7, %8, %9, %10, %11, %12, %13, %14, %15, " \
        " %16, %17, %18, %19, %20, %21, %22, %23, %24, %25, %26, %27, %28, %29, %30, %31}, [%32];" \
        : "=r"((r)[0]),  "=r"((r)[1]),  "=r"((r)[2]),  "=r"((r)[3]), \
          "=r"((r)[4]),  "=r"((r)[5]),  "=r"((r)[6]),  "=r"((r)[7]), \
          "=r"((r)[8]),  "=r"((r)[9]),  "=r"((r)[10]), "=r"((r)[11]), \
          "=r"((r)[12]), "=r"((r)[13]), "=r"((r)[14]), "=r"((r)[15]), \
          "=r"((r)[16]), "=r"((r)[17]), "=r"((r)[18]), "=r"((r)[19]), \
          "=r"((r)[20]), "=r"((r)[21]), "=r"((r)[22]), "=r"((r)[23]), \
          "=r"((r)[24]), "=r"((r)[25]), "=r"((r)[26]), "=r"((r)[27]), \
          "=r"((r)[28]), "=r"((r)[29]), "=r"((r)[30]), "=r"((r)[31]) \
        : "r"(addr))
#endif  // HAS_TC

// ---------------- weight prep: fp32 square matrix -> bf16 hi/lo, direct + transposed ----
__global__ void wprep_kernel(const float* __restrict__ W, int n,
                             __nv_bfloat16* __restrict__ dH, __nv_bfloat16* __restrict__ dL,
                             __nv_bfloat16* __restrict__ tH, __nv_bfloat16* __restrict__ tL) {
    int idx = blockIdx.x * 256 + threadIdx.x;
    if (idx >= n * n) return;
    int r = idx / n, c = idx % n;
    __nv_bfloat16 h, l;
    split_bf16(W[idx], h, l);
    dH[idx] = h; dL[idx] = l;
    tH[c * n + r] = h; tL[c * n + r] = l;
}

// heads batched: z selects the network, outputs strided by 65536
__global__ void wpreph_kernel(const float* __restrict__ W0, const float* __restrict__ W1,
                              const float* __restrict__ W2,
                              __nv_bfloat16* __restrict__ dH, __nv_bfloat16* __restrict__ dL,
                              __nv_bfloat16* __restrict__ tH, __nv_bfloat16* __restrict__ tL) {
    const int n = 256;
    int t = blockIdx.z;
    const float* W = (t == 0) ? W0 : (t == 1) ? W1 : W2;
    size_t o = (size_t)t * 65536;
    int idx = blockIdx.x * 256 + threadIdx.x;
    int r = idx / n, c = idx % n;
    __nv_bfloat16 h, l;
    split_bf16(W[idx], h, l);
    dH[o + idx] = h; dL[o + idx] = l;
    tH[o + c * n + r] = h; tL[o + c * n + r] = l;
}

// ---------------- fused layer-1 forward: all 4 networks, 8 samples per block ----------
// grid (m/8, 5): part 0-1 = pos column halves, parts 2-4 = heads.
// Each thread keeps its 7 W0 weights + bias in registers; q staged via shared.
__global__ __launch_bounds__(256) void fwd1all_kernel(
    const float* __restrict__ x,
    const float* __restrict__ pW0, const float* __restrict__ pb0,
    const float* __restrict__ hW00, const float* __restrict__ hW01,
    const float* __restrict__ hW02,
    const float* __restrict__ hb00, const float* __restrict__ hb01,
    const float* __restrict__ hb02,
    int m) {
    __shared__ float sq[8 * 7];
    const int tid = threadIdx.x;
    const int part = blockIdx.y;
    const int s0 = blockIdx.x * 8;
    if (tid < 56) {
        int sl = tid / 7, j = tid % 7;
        sq[tid] = x[(size_t)(s0 + sl) * 14 + j];
    }
    __syncthreads();

    const float *W0, *b0;
    float* H1;
    __nv_bfloat16 *H1h, *H1l;
    int width, n;
    size_t obase;
    if (part < 2) {
        W0 = pW0; b0 = pb0; width = 512; n = part * 256 + tid;
        H1 = g_H1p; H1h = g_H1ph; H1l = g_H1pl;
        obase = 0;
    } else {
        int t = part - 2;
        W0 = (t == 0) ? hW00 : (t == 1) ? hW01 : hW02;
        b0 = (t == 0) ? hb00 : (t == 1) ? hb01 : hb02;
        width = 256; n = tid;
        H1 = g_H1r; H1h = g_H1rh; H1l = g_H1rl;
        obase = (size_t)t * m * 256;
    }
    float w[7];
#pragma unroll
    for (int j = 0; j < 7; ++j) w[j] = W0[j * width + n];
    const float b = b0[n];
#pragma unroll
    for (int sl = 0; sl < 8; ++sl) {
        float z = b;
#pragma unroll
        for (int j = 0; j < 7; ++j) z += w[j] * sq[sl * 7 + j];
        float h = sigf(z);
        size_t o = obase + (size_t)(s0 + sl) * width + n;
        H1[o] = h;
        __nv_bfloat16 bh, bl;
        split_bf16(h, bh, bl);
        H1h[o] = bh; H1l[o] = bl;
    }
}

// ---------------- GEMM: C[M,N] = epi( A[M,K] @ B_nk[N,K]^T ), batched over z ----------
// A bf16 hi/lo [M,K] row-major; B bf16 hi/lo [N,K] row-major. blockIdx.z selects the
// batch member via strides (pos GEMMs: grid.z=1, strides ignored).
// tcgen05 path: tile 128x64, BK=64 chunks, SS kind::f16, fp32 TMEM accum,
//               3-term split Ah*Bh + Ah*Bl + Al*Bh, double-buffered + mbarrier.
// Fallback path (non-'a' PTX target): SIMT 128x64 register-tiled fp32 GEMM on (hi+lo).
// EPI==1: C = sigmoid(acc + bias[n]);  EPI==2: C = acc * h*(1-h), h = Hs[(row/O)*N + n]
#define TCG_SMEM_BYTES (1024 + 1024 + 2 * 49152)
template <int EPI>
__global__ __launch_bounds__(256)
void tc_gemm(int K, int N,
             const __nv_bfloat16* __restrict__ Ahi, const __nv_bfloat16* __restrict__ Alo,
             size_t aStr,
             const __nv_bfloat16* __restrict__ Bhi, const __nv_bfloat16* __restrict__ Blo,
             size_t bStr,
             const float* __restrict__ bias0, const float* __restrict__ bias1,
             const float* __restrict__ bias2,
             const float* __restrict__ Hs, size_t hStr, int O,
             float* __restrict__ C, size_t cStr) {
    const int t = blockIdx.z;
    Ahi += (size_t)t * aStr;  Alo += (size_t)t * aStr;
    Bhi += (size_t)t * bStr;  Blo += (size_t)t * bStr;
    const float* bias = (t == 0) ? bias0 : (t == 1) ? bias1 : bias2;
    if (Hs) Hs += (size_t)t * hStr;
    C += (size_t)t * cStr;

#if HAS_TC
    extern __shared__ char dsm[];
    uint32_t sb_raw = smem_u32(dsm);
    uint32_t sb = (sb_raw + 1023) & ~1023u;
    char* base = dsm + (sb - sb_raw);

    const int tid  = threadIdx.x;
    const int wid  = tid >> 5;
    const int lane = tid & 31;
    const int row0 = blockIdx.y * 128;
    const int col0 = blockIdx.x * 64;

    const uint32_t BAR0 = sb + 16, BAR1 = sb + 24;
    if (tid == 0) { MBAR_INIT(BAR0, 1); MBAR_INIT(BAR1, 1); }
    if (wid == 0) { TCG_ALLOC(sb, 128); TCG_RELINQ(); }
    __syncthreads();
    uint32_t tmem;
    asm volatile("ld.shared.b32 %0, [%1];" : "=r"(tmem) : "r"(sb));

    const uint32_t IDESC = (1u << 4) | (1u << 7) | (1u << 10) | (8u << 17) | (8u << 24);
    const int NC = K >> 6;
    int ph0 = 0, ph1 = 0;

    for (int kc = 0; kc < NC; ++kc) {
        const int b = kc & 1;
        if (kc >= 2) {
            if (b == 0) { MBAR_WAIT(BAR0, ph0); ph0 ^= 1; }
            else        { MBAR_WAIT(BAR1, ph1); ph1 ^= 1; }
        }
        char* Ah = base + 1024 + b * 49152;
        char* Al = Ah + 16384;
        char* Bh = Ah + 32768;
        char* Bl = Ah + 40960;
        const int kb = kc * 64;
#pragma unroll
        for (int rep = 0; rep < 4; ++rep) {
            int idx = rep * 256 + tid;
            int r = idx >> 3, u = idx & 7;
            size_t g = (size_t)(row0 + r) * K + kb + u * 8;
            uint32_t off = (uint32_t)(r * 128 + u * 16);
            off ^= (off >> 3) & 0x70;
            *(uint4*)(Ah + off) = *(const uint4*)(Ahi + g);
            *(uint4*)(Al + off) = *(const uint4*)(Alo + g);
        }
#pragma unroll
        for (int rep = 0; rep < 2; ++rep) {
            int idx = rep * 256 + tid;
            int r = idx >> 3, u = idx & 7;
            size_t g = (size_t)(col0 + r) * K + kb + u * 8;
            uint32_t off = (uint32_t)(r * 128 + u * 16);
            off ^= (off >> 3) & 0x70;
            *(uint4*)(Bh + off) = *(const uint4*)(Bhi + g);
            *(uint4*)(Bl + off) = *(const uint4*)(Blo + g);
        }
        __syncthreads();
        if (wid == 0) {
            asm volatile("fence.proxy.async.shared::cta;" ::: "memory");
            if (elect1()) {
                uint32_t abase = sb + 1024 + b * 49152;
                uint64_t adh = sdesc(abase);
                uint64_t adl = adh + (16384 >> 4);
                uint64_t bdh = adh + (32768 >> 4);
                uint64_t bdl = adh + (40960 >> 4);
#pragma unroll
                for (int ks = 0; ks < 4; ++ks) {
                    uint64_t o = (uint64_t)(ks * 2);
                    uint32_t e0 = (kc | ks) ? 1u : 0u;
                    mma_f16_ss(tmem, adh + o, bdh + o, IDESC, e0);
                    mma_f16_ss(tmem, adh + o, bdl + o, IDESC, 1u);
                    mma_f16_ss(tmem, adl + o, bdh + o, IDESC, 1u);
                }
                TCG_COMMIT(b ? BAR1 : BAR0);
            }
        }
    }
    MBAR_WAIT(BAR0, ph0);
    MBAR_WAIT(BAR1, ph1);
    TCG_FENCE_AFTER();

    if (wid < 4) {
        uint32_t d[64];
        TCG_LD32(d, tmem);
        TCG_LD32(d + 32, tmem + 32);
        TCG_WAIT_LD();
        int row = row0 + wid * 32 + lane;
        float* cp = C + (size_t)row * N + col0;
        if (EPI == 1) {
#pragma unroll
            for (int c4 = 0; c4 < 16; ++c4) {
                float4 bb = *(const float4*)(bias + col0 + c4 * 4);
                float4 v;
                v.x = sigf(__uint_as_float(d[c4 * 4 + 0]) + bb.x);
                v.y = sigf(__uint_as_float(d[c4 * 4 + 1]) + bb.y);
                v.z = sigf(__uint_as_float(d[c4 * 4 + 2]) + bb.z);
                v.w = sigf(__uint_as_float(d[c4 * 4 + 3]) + bb.w);
                *(float4*)(cp + c4 * 4) = v;
            }
        } else {
            int srow = row / O;
            const float* hp = Hs + (size_t)srow * N + col0;
#pragma unroll
            for (int c4 = 0; c4 < 16; ++c4) {
                float4 h = *(const float4*)(hp + c4 * 4);
                float4 v;
                v.x = __uint_as_float(d[c4 * 4 + 0]) * h.x * (1.0f - h.x);
                v.y = __uint_as_float(d[c4 * 4 + 1]) * h.y * (1.0f - h.y);
                v.z = __uint_as_float(d[c4 * 4 + 2]) * h.z * (1.0f - h.z);
                v.w = __uint_as_float(d[c4 * 4 + 3]) * h.w * (1.0f - h.w);
                *(float4*)(cp + c4 * 4) = v;
            }
        }
    }
    __syncthreads();
    if (wid == 0) TCG_DEALLOC(tmem, 128);
#else
    // ---------------- SIMT fallback: fp32 register-tiled 128x64 GEMM on (hi+lo) --------
    extern __shared__ char dsm[];
    float* As = (float*)dsm;          // [32][128]
    float* Bs = As + 32 * 128;        // [32][64]

    const int tid = threadIdx.x;
    const int tx = tid & 15;
    const int ty = tid >> 4;
    const int row0 = blockIdx.y * 128;
    const int col0 = blockIdx.x * 64;

    float acc[8][4];
#pragma unroll
    for (int i = 0; i < 8; ++i)
#pragma unroll
        for (int j = 0; j < 4; ++j) acc[i][j] = 0.0f;

    for (int kb = 0; kb < K; kb += 32) {
        __syncthreads();
#pragma unroll
        for (int v = 0; v < 2; ++v) {
            int i = tid * 2 + v;
            int r = i >> 2, u = (i & 3) * 8;
            size_t ga = (size_t)(row0 + r) * K + kb + u;
            uint4 h4 = *(const uint4*)(Ahi + ga);
            uint4 l4 = *(const uint4*)(Alo + ga);
            float f[8];
            cvt2(h4.x, l4.x, f[0], f[1]); cvt2(h4.y, l4.y, f[2], f[3]);
            cvt2(h4.z, l4.z, f[4], f[5]); cvt2(h4.w, l4.w, f[6], f[7]);
#pragma unroll
            for (int e = 0; e < 8; ++e) As[(u + e) * 128 + r] = f[e];
        }
        {
            int r = tid >> 2, u = (tid & 3) * 8;
            size_t gb = (size_t)(col0 + r) * K + kb + u;
            uint4 h4 = *(const uint4*)(Bhi + gb);
            uint4 l4 = *(const uint4*)(Blo + gb);
            float f[8];
            cvt2(h4.x, l4.x, f[0], f[1]); cvt2(h4.y, l4.y, f[2], f[3]);
            cvt2(h4.z, l4.z, f[4], f[5]); cvt2(h4.w, l4.w, f[6], f[7]);
#pragma unroll
            for (int e = 0; e < 8; ++e) Bs[(u + e) * 64 + r] = f[e];
        }
        __syncthreads();
#pragma unroll
        for (int k = 0; k < 32; ++k) {
            float a[8], b[4];
            *(float4*)(a + 0) = *(const float4*)&As[k * 128 + ty * 8];
            *(float4*)(a + 4) = *(const float4*)&As[k * 128 + ty * 8 + 4];
            *(float4*)(b + 0) = *(const float4*)&Bs[k * 64 + tx * 4];
#pragma unroll
            for (int i = 0; i < 8; ++i)
#pragma unroll
                for (int j = 0; j < 4; ++j) acc[i][j] += a[i] * b[j];
        }
    }

    const int r0 = row0 + ty * 8;
    const int c0 = col0 + tx * 4;
    if (EPI == 1) {
        float4 bb = *(const float4*)(bias + c0);
#pragma unroll
        for (int i = 0; i < 8; ++i) {
            float4 v;
            v.x = sigf(acc[i][0] + bb.x);
            v.y = sigf(acc[i][1] + bb.y);
            v.z = sigf(acc[i][2] + bb.z);
            v.w = sigf(acc[i][3] + bb.w);
            *(float4*)(C + (size_t)(r0 + i) * N + c0) = v;
        }
    } else {
#pragma unroll
        for (int i = 0; i < 8; ++i) {
            int srow = (r0 + i) / O;
            float4 h = *(const float4*)(Hs + (size_t)srow * N + c0);
            float4 v;
            v.x = acc[i][0] * h.x * (1.0f - h.x);
            v.y = acc[i][1] * h.y * (1.0f - h.y);
            v.z = acc[i][2] * h.z * (1.0f - h.z);
            v.w = acc[i][3] * h.w * (1.0f - h.w);
            *(float4*)(C + (size_t)(r0 + i) * N + c0) = v;
        }
    }
#endif
}

// ---------------- seed kernel: output-layer dots + backward seeds (vectorized) ----------
__global__ __launch_bounds__(128) void seed_kernel(
    const float* __restrict__ W2p, const float* __restrict__ b2p,
    const float* __restrict__ W2r0, const float* __restrict__ b2r0,
    const float* __restrict__ W2r1, const float* __restrict__ b2r1,
    const float* __restrict__ W2r2, const float* __restrict__ b2r2,
    int m) {
    const int lane = threadIdx.x & 31;
    const int s = blockIdx.x * 4 + (threadIdx.x >> 5);

    {
        const float* h2 = g_H2p + (size_t)s * 512;
        __nv_bfloat16* aph = g_Aph + (size_t)s * 1536;
        __nv_bfloat16* apl = g_Apl + (size_t)s * 1536;
        float a0 = 0.f, a1 = 0.f, a2 = 0.f;
#pragma unroll
        for (int i0 = lane * 4; i0 < 512; i0 += 128) {
            float4 h4 = *(const float4*)(h2 + i0);
            float4 w0 = *(const float4*)(W2p + i0 * 3);
            float4 w1 = *(const float4*)(W2p + i0 * 3 + 4);
            float4 w2 = *(const float4*)(W2p + i0 * 3 + 8);
            float hv[4] = {h4.x, h4.y, h4.z, h4.w};
            float wv[12] = {w0.x, w0.y, w0.z, w0.w, w1.x, w1.y,
                            w1.z, w1.w, w2.x, w2.y, w2.z, w2.w};
            __nv_bfloat16 oh[3][4], ol[3][4];
#pragma unroll
            for (int e = 0; e < 4; ++e) {
                float h = hv[e], d = h * (1.0f - h);
                float wa = wv[e * 3], wb = wv[e * 3 + 1], wc = wv[e * 3 + 2];
                a0 += h * wa; a1 += h * wb; a2 += h * wc;
                split_bf16(d * wa, oh[0][e], ol[0][e]);
                split_bf16(d * wb, oh[1][e], ol[1][e]);
                split_bf16(d * wc, oh[2][e], ol[2][e]);
            }
#pragma unroll
            for (int o = 0; o < 3; ++o) {
                uint2 uh, ul;
                uh.x = pack_bf(oh[o][0], oh[o][1]); uh.y = pack_bf(oh[o][2], oh[o][3]);
                ul.x = pack_bf(ol[o][0], ol[o][1]); ul.y = pack_bf(ol[o][2], ol[o][3]);
                *(uint2*)(aph + o * 512 + i0) = uh;
                *(uint2*)(apl + o * 512 + i0) = ul;
            }
        }
        a0 = wred(a0); a1 = wred(a1); a2 = wred(a2);
        if (lane == 0) {
            g_aux[s * 9 + 0] = a0 + b2p[0];
            g_aux[s * 9 + 1] = a1 + b2p[1];
            g_aux[s * 9 + 2] = a2 + b2p[2];
        }
    }
    const float* W2h[3] = {W2r0, W2r1, W2r2};
    const float* b2h[3] = {b2r0, b2r1, b2r2};
#pragma unroll
    for (int t = 0; t < 3; ++t) {
        const float* h2 = g_H2r + ((size_t)t * m + s) * 256;
        __nv_bfloat16* arh = g_Arh + ((size_t)t * m + s) * 512;
        __nv_bfloat16* arl = g_Arl + ((size_t)t * m + s) * 512;
        const float* W = W2h[t];
        float a0 = 0.f, a1 = 0.f;
#pragma unroll
        for (int i0 = lane * 4; i0 < 256; i0 += 128) {
            float4 h4 = *(const float4*)(h2 + i0);
            float4 w0 = *(const float4*)(W + i0 * 2);
            float4 w1 = *(const float4*)(W + i0 * 2 + 4);
            float hv[4] = {h4.x, h4.y, h4.z, h4.w};
            float wv[8] = {w0.x, w0.y, w0.z, w0.w, w1.x, w1.y, w1.z, w1.w};
            __nv_bfloat16 oh[2][4], ol[2][4];
#pragma unroll
            for (int e = 0; e < 4; ++e) {
                float h = hv[e], d = h * (1.0f - h);
                float wa = wv[e * 2], wb = wv[e * 2 + 1];
                a0 += h * wa; a1 += h * wb;
                split_bf16(d * wa, oh[0][e], ol[0][e]);
                split_bf16(d * wb, oh[1][e], ol[1][e]);
            }
#pragma unroll
            for (int o = 0; o < 2; ++o) {
                uint2 uh, ul;
                uh.x = pack_bf(oh[o][0], oh[o][1]); uh.y = pack_bf(oh[o][2], oh[o][3]);
                ul.x = pack_bf(ol[o][0], ol[o][1]); ul.y = pack_bf(ol[o][2], ol[o][3]);
                *(uint2*)(arh + o * 256 + i0) = uh;
                *(uint2*)(arl + o * 256 + i0) = ul;
            }
        }
        a0 = wred(a0); a1 = wred(a1);
        if (lane == 0) {
            g_aux[s * 9 + 3 + 2 * t] = a0 + b2h[t][0];
            g_aux[s * 9 + 4 + 2 * t] = a1 + b2h[t][1];
        }
    }
}

// ---------------- final kernel: J projection to inputs, chain rule, assembly ----------------
__global__ __launch_bounds__(128) void final_kernel(
    const float* __restrict__ x,
    const float* __restrict__ W0p,
    const float* __restrict__ W0r0, const float* __restrict__ W0r1, const float* __restrict__ W0r2,
    float* __restrict__ out, int m) {
    __shared__ float sWp[7 * 512];
    __shared__ float sWr[3][7 * 256];
    for (int i = threadIdx.x; i < 7 * 512; i += 128) sWp[i] = W0p[i];
    for (int i = threadIdx.x; i < 7 * 256; i += 128) {
        sWr[0][i] = W0r0[i]; sWr[1][i] = W0r1[i]; sWr[2][i] = W0r2[i];
    }
    __syncthreads();

    const int lane = threadIdx.x & 31;
    const int s = blockIdx.x * 4 + (threadIdx.x >> 5);

    float accP[21];
#pragma unroll
    for (int p = 0; p < 21; ++p) accP[p] = 0.0f;
    {
        const float* g = g_G1p + (size_t)s * 1536;
        for (int i = lane; i < 512; i += 32) {
            float g0 = g[i], g1 = g[512 + i], g2 = g[1024 + i];
#pragma unroll
            for (int j = 0; j < 7; ++j) {
                float w = sWp[j * 512 + i];
                accP[j]      += g0 * w;
                accP[7 + j]  += g1 * w;
                accP[14 + j] += g2 * w;
            }
        }
    }
    float accH[42];
#pragma unroll
    for (int p = 0; p < 42; ++p) accH[p] = 0.0f;
#pragma unroll
    for (int t = 0; t < 3; ++t) {
        const float* gr = g_G1r + ((size_t)t * m + s) * 512;
        for (int i = lane; i < 256; i += 32) {
            float g0 = gr[i], g1 = gr[256 + i];
#pragma unroll
            for (int j = 0; j < 7; ++j) {
                float w = sWr[t][j * 256 + i];
                accH[t * 14 + j]     += g0 * w;
                accH[t * 14 + 7 + j] += g1 * w;
            }
        }
    }
#pragma unroll
    for (int p = 0; p < 21; ++p) accP[p] = wred(accP[p]);
#pragma unroll
    for (int p = 0; p < 42; ++p) accH[p] = wred(accH[p]);

    if (lane == 0) {
        float qd[7];
#pragma unroll
        for (int j = 0; j < 7; ++j) qd[j] = x[(size_t)s * 14 + 7 + j];
        float P0 = g_aux[s * 9 + 0], P1 = g_aux[s * 9 + 1], P2 = g_aux[s * 9 + 2];

        float sn[3], cs[3], ang[3];
        float R0[3][7], R1[3][7], R2[3][7];
#pragma unroll
        for (int t = 0; t < 3; ++t) {
            float y0 = g_aux[s * 9 + 3 + 2 * t];
            float y1 = g_aux[s * 9 + 4 + 2 * t];
            float s_ = sinf(y0), cy0 = cosf(y0);
            float c_ = cosf(y1), sy1 = sinf(y1);
            sn[t] = s_; cs[t] = c_;
            ang[t] = atan2f(s_, c_);
            float inv = 1.0f / (s_ * s_ + c_ * c_);
#pragma unroll
            for (int j = 0; j < 7; ++j) {
                float j0 = accH[t * 14 + j], j1 = accH[t * 14 + 7 + j];
                R0[t][j] = cy0 * j0;
                R1[t][j] = -sy1 * j1;
                R2[t][j] = inv * (c_ * cy0 * j0 + s_ * sy1 * j1);
            }
        }
        float velP[3], v0[3], v1[3];
#pragma unroll
        for (int o = 0; o < 3; ++o) {
            float a = 0.f;
#pragma unroll
            for (int j = 0; j < 7; ++j) a += accP[o * 7 + j] * qd[j];
            velP[o] = a;
        }
#pragma unroll
        for (int t = 0; t < 3; ++t) {
            float a = 0.f, b = 0.f;
#pragma unroll
            for (int j = 0; j < 7; ++j) { a += R0[t][j] * qd[j]; b += R1[t][j] * qd[j]; }
            v0[t] = a; v1[t] = b;
        }

        float* o1 = out + (size_t)s * 18;
        o1[0] = P0; o1[1] = P1; o1[2] = P2;
#pragma unroll
        for (int t = 0; t < 3; ++t) {
            o1[3 + t] = sn[t]; o1[6 + t] = cs[t];
            o1[12 + t] = v0[t]; o1[15 + t] = v1[t];
        }
#pragma unroll
        for (int o = 0; o < 3; ++o) o1[9 + o] = velP[o];

        float* J = out + (size_t)m * 18 + (size_t)s * 63;
#pragma unroll
        for (int p = 0; p < 21; ++p) J[p] = accP[p];
#pragma unroll
        for (int t = 0; t < 3; ++t)
#pragma unroll
            for (int j = 0; j < 7; ++j) {
                J[(3 + t) * 7 + j] = R0[t][j];
                J[(6 + t) * 7 + j] = R1[t][j];
            }

        float* oa = out + (size_t)m * 81 + (size_t)s * 6;
        oa[0] = P0; oa[1] = P1; oa[2] = P2;
#pragma unroll
        for (int t = 0; t < 3; ++t) oa[3 + t] = ang[t];

        float* Ja = out + (size_t)m * 87 + (size_t)s * 42;
#pragma unroll
        for (int p = 0; p < 21; ++p) Ja[p] = accP[p];
#pragma unroll
        for (int t = 0; t < 3; ++t)
#pragma unroll
            for (int j = 0; j < 7; ++j) Ja[(3 + t) * 7 + j] = R2[t][j];
    }
}

// ---------------- launch ----------------
extern "C" void kernel_launch(void* const* d_in, const int* in_sizes, int n_in,
                              void* d_out, int out_size) {
    const float* x   = (const float*)d_in[0];
    const float* pW0 = (const float*)d_in[1];
    const float* pb0 = (const float*)d_in[2];
    const float* pW1 = (const float*)d_in[3];
    const float* pb1 = (const float*)d_in[4];
    const float* pW2 = (const float*)d_in[5];
    const float* pb2 = (const float*)d_in[6];
    const float* hW0[3]; const float* hb0[3];
    const float* hW1[3]; const float* hb1[3];
    const float* hW2[3]; const float* hb2[3];
    for (int t = 0; t < 3; ++t) {
        int base = 7 + t * 6;
        hW0[t] = (const float*)d_in[base + 0];
        hb0[t] = (const float*)d_in[base + 1];
        hW1[t] = (const float*)d_in[base + 2];
        hb1[t] = (const float*)d_in[base + 3];
        hW2[t] = (const float*)d_in[base + 4];
        hb2[t] = (const float*)d_in[base + 5];
    }
    const int m = in_sizes[0] / 14;  // 16384
    float* out = (float*)d_out;
    (void)n_in; (void)out_size;

    float *H1p, *G1p;
    __nv_bfloat16 *H1ph, *H1pl, *H1rh, *H1rl, *Aph, *Apl, *Arh, *Arl;
    float *H1r, *H2p, *H2r, *G1r;
    __nv_bfloat16 *W1dh, *W1dl, *W1th, *W1tl, *Wrdh, *Wrdl, *Wrth, *Wrtl;
    cudaGetSymbolAddress((void**)&H1p,  g_H1p);
    cudaGetSymbolAddress((void**)&H2p,  g_H2p);
    cudaGetSymbolAddress((void**)&H1r,  g_H1r);
    cudaGetSymbolAddress((void**)&H2r,  g_H2r);
    cudaGetSymbolAddress((void**)&G1p,  g_G1p);
    cudaGetSymbolAddress((void**)&G1r,  g_G1r);
    cudaGetSymbolAddress((void**)&H1ph, g_H1ph);
    cudaGetSymbolAddress((void**)&H1pl, g_H1pl);
    cudaGetSymbolAddress((void**)&H1rh, g_H1rh);
    cudaGetSymbolAddress((void**)&H1rl, g_H1rl);
    cudaGetSymbolAddress((void**)&Aph,  g_Aph);
    cudaGetSymbolAddress((void**)&Apl,  g_Apl);
    cudaGetSymbolAddress((void**)&Arh,  g_Arh);
    cudaGetSymbolAddress((void**)&Arl,  g_Arl);
    cudaGetSymbolAddress((void**)&W1dh, g_W1d_h);
    cudaGetSymbolAddress((void**)&W1dl, g_W1d_l);
    cudaGetSymbolAddress((void**)&W1th, g_W1t_h);
    cudaGetSymbolAddress((void**)&W1tl, g_W1t_l);
    cudaGetSymbolAddress((void**)&Wrdh, g_Wrd_h);
    cudaGetSymbolAddress((void**)&Wrdl, g_Wrd_l);
    cudaGetSymbolAddress((void**)&Wrth, g_Wrt_h);
    cudaGetSymbolAddress((void**)&Wrtl, g_Wrt_l);

    cudaFuncSetAttribute(tc_gemm<1>, cudaFuncAttributeMaxDynamicSharedMemorySize, TCG_SMEM_BYTES);
    cudaFuncSetAttribute(tc_gemm<2>, cudaFuncAttributeMaxDynamicSharedMemorySize, TCG_SMEM_BYTES);

    // weight prep: bf16 hi/lo, direct ([j][i]) and transposed ([n][k]) layouts
    wprep_kernel<<<(512 * 512 + 255) / 256, 256>>>(pW1, 512, W1dh, W1dl, W1th, W1tl);
    wpreph_kernel<<<dim3((256 * 256) / 256, 1, 3), 256>>>(
        hW1[0], hW1[1], hW1[2], Wrdh, Wrdl, Wrth, Wrtl);

    // fused layer-1 forward (all 4 networks, 8 samples/block)
    fwd1all_kernel<<<dim3(m / 8, 5), 256>>>(x, pW0, pb0, hW0[0], hW0[1], hW0[2],
                                            hb0[0], hb0[1], hb0[2], m);

    // layer-2 forward GEMMs (sigmoid epilogue), 128x64 tiles
    tc_gemm<1><<<dim3(8, m / 128, 1), 256, TCG_SMEM_BYTES>>>(
        512, 512, H1ph, H1pl, 0, W1th, W1tl, 0, pb1, pb1, pb1, nullptr, 0, 1, H2p, 0);
    tc_gemm<1><<<dim3(4, m / 128, 3), 256, TCG_SMEM_BYTES>>>(
        256, 256, H1rh, H1rl, (size_t)m * 256, Wrth, Wrtl, 65536,
        hb1[0], hb1[1], hb1[2], nullptr, 0, 1, H2r, (size_t)m * 256);

    // output-layer dots + backward seeds (bf16 hi/lo, vectorized)
    seed_kernel<<<m / 4, 128>>>(pW2, pb2, hW2[0], hb2[0], hW2[1], hb2[1], hW2[2], hb2[2], m);

    // backward GEMMs (dsigmoid epilogue): G1 = (A @ W1^T) .* sigma1'
    tc_gemm<2><<<dim3(8, (3 * m) / 128, 1), 256, TCG_SMEM_BYTES>>>(
        512, 512, Aph, Apl, 0, W1dh, W1dl, 0, nullptr, nullptr, nullptr,
        H1p, 0, 3, G1p, 0);
    tc_gemm<2><<<dim3(4, (2 * m) / 128, 3), 256, TCG_SMEM_BYTES>>>(
        256, 256, Arh, Arl, (size_t)m * 512, Wrdh, Wrdl, 65536,
        nullptr, nullptr, nullptr, H1r, (size_t)m * 256, 2, G1r, (size_t)m * 512);

    // input-side projection + trig chain rule + output assembly
    final_kernel<<<m / 4, 128>>>(x, pW0, hW0[0], hW0[1], hW0[2], out, m);
}

// round 17
// speedup vs baseline: 1.0192x; 1.0192x over previous
#include <cuda_runtime.h>
#include <cuda_bf16.h>
#include <math.h>
#include <stdint.h>

#define MSAMP 16384

// tcgen05 is only encodable on arch-specific / family-specific Blackwell targets.
// A plain compute_103 pass (no 'a' suffix) gets a SIMT fallback body instead.
#if !defined(__CUDA_ARCH__) || defined(__CUDA_ARCH_FEAT_SM103_ALL) || \
    defined(__CUDA_ARCH_FEAT_SM100_ALL) || defined(__CUDA_ARCH_FEAT_SM101_ALL) || \
    (defined(__CUDA_ARCH_FAMILY_SPECIFIC__) && (__CUDA_ARCH_FAMILY_SPECIFIC__ >= 1000))
#define HAS_TC 1
#else
#define HAS_TC 0
#endif

// ---------------- scratch (device globals; no runtime allocation) ----------------
__device__ float g_H1p[MSAMP * 512];
__device__ float g_H2p[MSAMP * 512];
__device__ float g_H1r[3 * MSAMP * 256];
__device__ float g_H2r[3 * MSAMP * 256];
__device__ float g_G1p[MSAMP * 3 * 512];
__device__ float g_G1r[3 * MSAMP * 2 * 256];
__device__ float g_aux[MSAMP * 9];

__device__ __nv_bfloat16 g_H1ph[MSAMP * 512],       g_H1pl[MSAMP * 512];
__device__ __nv_bfloat16 g_H1rh[3 * MSAMP * 256],   g_H1rl[3 * MSAMP * 256];
__device__ __nv_bfloat16 g_Aph [MSAMP * 3 * 512],   g_Apl [MSAMP * 3 * 512];
__device__ __nv_bfloat16 g_Arh [3 * MSAMP * 2 * 256], g_Arl[3 * MSAMP * 2 * 256];
__device__ __nv_bfloat16 g_W1d_h[512 * 512], g_W1d_l[512 * 512];   // W1 direct  [j][i]
__device__ __nv_bfloat16 g_W1t_h[512 * 512], g_W1t_l[512 * 512];   // W1 transp  [n][k]
__device__ __nv_bfloat16 g_Wrd_h[3 * 256 * 256], g_Wrd_l[3 * 256 * 256];
__device__ __nv_bfloat16 g_Wrt_h[3 * 256 * 256], g_Wrt_l[3 * 256 * 256];

__device__ __forceinline__ float sigf(float z) { return 1.0f / (1.0f + expf(-z)); }

__device__ __forceinline__ float wred(float v) {
#pragma unroll
    for (int o = 16; o; o >>= 1) v += __shfl_xor_sync(0xffffffffu, v, o);
    return v;
}

__device__ __forceinline__ void split_bf16(float v, __nv_bfloat16& h, __nv_bfloat16& l) {
    h = __float2bfloat16(v);
    l = __float2bfloat16(v - __bfloat162float(h));
}

__device__ __forceinline__ uint32_t pack_bf(__nv_bfloat16 a, __nv_bfloat16 b) {
    return (uint32_t)__bfloat16_as_ushort(a) | ((uint32_t)__bfloat16_as_ushort(b) << 16);
}

// two packed bf16 (hi word / lo word of u) + their lo-correction -> two fp32
__device__ __forceinline__ void cvt2(uint32_t h, uint32_t l, float& f0, float& f1) {
    f0 = __uint_as_float(h << 16)         + __uint_as_float(l << 16);
    f1 = __uint_as_float(h & 0xffff0000u) + __uint_as_float(l & 0xffff0000u);
}

// ---------------- PTX helpers (sm_103a tcgen05) ----------------
__device__ __forceinline__ uint32_t smem_u32(const void* p) {
    uint32_t a;
    asm("{ .reg .u64 t; cvta.to.shared.u64 t, %1; cvt.u32.u64 %0, t; }" : "=r"(a) : "l"(p));
    return a;
}
#define MBAR_INIT(addr, cnt) \
    asm volatile("mbarrier.init.shared.b64 [%0], %1;" :: "r"(addr), "r"((uint32_t)(cnt)) : "memory")
#define MBAR_WAIT(addr, par) do {                                                            \
    uint32_t _m = (addr), _p = (uint32_t)(par), _d;                                          \
    asm volatile("{\n\t.reg .pred p;\n\t"                                                    \
        "mbarrier.try_wait.parity.acquire.cta.shared::cta.b64 p, [%1], %2;\n\t"              \
        "selp.b32 %0,1,0,p;\n\t}" : "=r"(_d) : "r"(_m), "r"(_p) : "memory");                 \
    while (!_d) {                                                                            \
        asm volatile("{\n\t.reg .pred p;\n\t"                                                \
            "mbarrier.try_wait.parity.acquire.cta.shared::cta.b64 p, [%1], %2, 0x989680;\n\t"\
            "selp.b32 %0,1,0,p;\n\t}" : "=r"(_d) : "r"(_m), "r"(_p) : "memory");             \
    }                                                                                        \
} while (0)

#if HAS_TC
__device__ __forceinline__ uint32_t elect1() {
    uint32_t p;
    asm volatile("{\n\t.reg .pred p;\n\telect.sync _|p, 0xFFFFFFFF;\n\tselp.b32 %0,1,0,p;\n\t}" : "=r"(p));
    return p;
}
__device__ __forceinline__ uint64_t sdesc(uint32_t addr) {
    return ((uint64_t)2 << 61) | ((uint64_t)1 << 46) | ((uint64_t)64 << 32) |
           ((uint64_t)1 << 16) | ((addr >> 4) & 0x3FFF);
}
__device__ __forceinline__ void mma_f16_ss(uint32_t d, uint64_t ad, uint64_t bd,
                                           uint32_t idesc, uint32_t en) {
    asm volatile(
        "{\n\t.reg .pred p;\n\tsetp.ne.u32 p, %5, 0;\n\t"
        "tcgen05.mma.cta_group::1.kind::f16 [%0], %1, %2, %3, {%4,%4,%4,%4}, p;\n\t}"
        :: "r"(d), "l"(ad), "l"(bd), "r"(idesc), "r"(0u), "r"(en) : "memory");
}
#define TCG_ALLOC(smem_addr, n) \
    asm volatile("tcgen05.alloc.cta_group::1.sync.aligned.shared::cta.b32 [%0], %1;" \
                 :: "r"(smem_addr), "r"((uint32_t)(n)) : "memory")
#define TCG_RELINQ() \
    asm volatile("tcgen05.relinquish_alloc_permit.cta_group::1.sync.aligned;")
#define TCG_DEALLOC(t, n) \
    asm volatile("tcgen05.dealloc.cta_group::1.sync.aligned.b32 %0, %1;" :: "r"(t), "r"((uint32_t)(n)))
#define TCG_COMMIT(bar) \
    asm volatile("tcgen05.commit.cta_group::1.mbarrier::arrive::one.shared::cluster.b64 [%0];" \
                 :: "r"(bar) : "memory")
#define TCG_FENCE_AFTER() asm volatile("tcgen05.fence::after_thread_sync;" ::: "memory")
#define TCG_WAIT_LD()     asm volatile("tcgen05.wait::ld.sync.aligned;" ::: "memory")
#define TCG_LD32(r, addr) \
    asm volatile("tcgen05.ld.sync.aligned.32x32b.x32.b32 " \
        "{%0, %1, %2, %3, %4, %5, %6, %7, %8, %9, %10, %11, %12, %13, %14, %15, " \
        " %16, %17, %18, %19, %20, %21, %22, %23, %24, %25, %26, %27, %28, %29, %30, %31}, [%32];" \
        : "=r"((r)[0]),  "=r"((r)[1]),  "=r"((r)[2]),  "=r"((r)[3]), \
          "=r"((r)[4]),  "=r"((r)[5]),  "=r"((r)[6]),  "=r"((r)[7]), \
          "=r"((r)[8]),  "=r"((r)[9]),  "=r"((r)[10]), "=r"((r)[11]), \
          "=r"((r)[12]), "=r"((r)[13]), "=r"((r)[14]), "=r"((r)[15]), \
          "=r"((r)[16]), "=r"((r)[17]), "=r"((r)[18]), "=r"((r)[19]), \
          "=r"((r)[20]), "=r"((r)[21]), "=r"((r)[22]), "=r"((r)[23]), \
          "=r"((r)[24]), "=r"((r)[25]), "=r"((r)[26]), "=r"((r)[27]), \
          "=r"((r)[28]), "=r"((r)[29]), "=r"((r)[30]), "=r"((r)[31]) \
        : "r"(addr))
#endif  // HAS_TC

// ---------------- weight prep: fp32 square matrix -> bf16 hi/lo, direct + transposed ----
__global__ void wprep_kernel(const float* __restrict__ W, int n,
                             __nv_bfloat16* __restrict__ dH, __nv_bfloat16* __restrict__ dL,
                             __nv_bfloat16* __restrict__ tH, __nv_bfloat16* __restrict__ tL) {
    int idx = blockIdx.x * 256 + threadIdx.x;
    if (idx >= n * n) return;
    int r = idx / n, c = idx % n;
    __nv_bfloat16 h, l;
    split_bf16(W[idx], h, l);
    dH[idx] = h; dL[idx] = l;
    tH[c * n + r] = h; tL[c * n + r] = l;
}

// heads batched: z selects the network, outputs strided by 65536
__global__ void wpreph_kernel(const float* __restrict__ W0, const float* __restrict__ W1,
                              const float* __restrict__ W2,
                              __nv_bfloat16* __restrict__ dH, __nv_bfloat16* __restrict__ dL,
                              __nv_bfloat16* __restrict__ tH, __nv_bfloat16* __restrict__ tL) {
    const int n = 256;
    int t = blockIdx.z;
    const float* W = (t == 0) ? W0 : (t == 1) ? W1 : W2;
    size_t o = (size_t)t * 65536;
    int idx = blockIdx.x * 256 + threadIdx.x;
    int r = idx / n, c = idx % n;
    __nv_bfloat16 h, l;
    split_bf16(W[idx], h, l);
    dH[o + idx] = h; dL[o + idx] = l;
    tH[o + c * n + r] = h; tL[o + c * n + r] = l;
}

// ---------------- fused layer-1 forward: all 4 networks, 8 samples per block ----------
// grid (m/8, 5): part 0-1 = pos column halves, parts 2-4 = heads.
// Each thread keeps its 7 W0 weights + bias in registers; q staged via shared.
__global__ __launch_bounds__(256) void fwd1all_kernel(
    const float* __restrict__ x,
    const float* __restrict__ pW0, const float* __restrict__ pb0,
    const float* __restrict__ hW00, const float* __restrict__ hW01,
    const float* __restrict__ hW02,
    const float* __restrict__ hb00, const float* __restrict__ hb01,
    const float* __restrict__ hb02,
    int m) {
    __shared__ float sq[8 * 7];
    const int tid = threadIdx.x;
    const int part = blockIdx.y;
    const int s0 = blockIdx.x * 8;
    if (tid < 56) {
        int sl = tid / 7, j = tid % 7;
        sq[tid] = x[(size_t)(s0 + sl) * 14 + j];
    }
    __syncthreads();

    const float *W0, *b0;
    float* H1;
    __nv_bfloat16 *H1h, *H1l;
    int width, n;
    size_t obase;
    if (part < 2) {
        W0 = pW0; b0 = pb0; width = 512; n = part * 256 + tid;
        H1 = g_H1p; H1h = g_H1ph; H1l = g_H1pl;
        obase = 0;
    } else {
        int t = part - 2;
        W0 = (t == 0) ? hW00 : (t == 1) ? hW01 : hW02;
        b0 = (t == 0) ? hb00 : (t == 1) ? hb01 : hb02;
        width = 256; n = tid;
        H1 = g_H1r; H1h = g_H1rh; H1l = g_H1rl;
        obase = (size_t)t * m * 256;
    }
    float w[7];
#pragma unroll
    for (int j = 0; j < 7; ++j) w[j] = W0[j * width + n];
    const float b = b0[n];
#pragma unroll
    for (int sl = 0; sl < 8; ++sl) {
        float z = b;
#pragma unroll
        for (int j = 0; j < 7; ++j) z += w[j] * sq[sl * 7 + j];
        float h = sigf(z);
        size_t o = obase + (size_t)(s0 + sl) * width + n;
        H1[o] = h;
        __nv_bfloat16 bh, bl;
        split_bf16(h, bh, bl);
        H1h[o] = bh; H1l[o] = bl;
    }
}

// ---------------- GEMM: C[M,N] = epi( A[M,K] @ B_nk[N,K]^T ), batched over z ----------
// A bf16 hi/lo [M,K] row-major; B bf16 hi/lo [N,K] row-major. blockIdx.z selects the
// batch member via strides (pos GEMMs: grid.z=1, strides ignored).
// tcgen05 path: tile 128x64, BK=64 chunks, SS kind::f16, fp32 TMEM accum,
//               3-term split Ah*Bh + Ah*Bl + Al*Bh, double-buffered + mbarrier.
// Fallback path (non-'a' PTX target): SIMT 128x64 register-tiled fp32 GEMM on (hi+lo).
// EPI==1: C = sigmoid(acc + bias[n]);  EPI==2: C = acc * h*(1-h), h = Hs[(row/O)*N + n]
#define TCG_SMEM_BYTES (1024 + 1024 + 2 * 49152)
template <int EPI>
__global__ __launch_bounds__(256)
void tc_gemm(int K, int N,
             const __nv_bfloat16* __restrict__ Ahi, const __nv_bfloat16* __restrict__ Alo,
             size_t aStr,
             const __nv_bfloat16* __restrict__ Bhi, const __nv_bfloat16* __restrict__ Blo,
             size_t bStr,
             const float* __restrict__ bias0, const float* __restrict__ bias1,
             const float* __restrict__ bias2,
             const float* __restrict__ Hs, size_t hStr, int O,
             float* __restrict__ C, size_t cStr) {
    const int t = blockIdx.z;
    Ahi += (size_t)t * aStr;  Alo += (size_t)t * aStr;
    Bhi += (size_t)t * bStr;  Blo += (size_t)t * bStr;
    const float* bias = (t == 0) ? bias0 : (t == 1) ? bias1 : bias2;
    if (Hs) Hs += (size_t)t * hStr;
    C += (size_t)t * cStr;

#if HAS_TC
    extern __shared__ char dsm[];
    uint32_t sb_raw = smem_u32(dsm);
    uint32_t sb = (sb_raw + 1023) & ~1023u;
    char* base = dsm + (sb - sb_raw);

    const int tid  = threadIdx.x;
    const int wid  = tid >> 5;
    const int lane = tid & 31;
    const int row0 = blockIdx.y * 128;
    const int col0 = blockIdx.x * 64;

    const uint32_t BAR0 = sb + 16, BAR1 = sb + 24;
    if (tid == 0) { MBAR_INIT(BAR0, 1); MBAR_INIT(BAR1, 1); }
    if (wid == 0) { TCG_ALLOC(sb, 128); TCG_RELINQ(); }
    __syncthreads();
    uint32_t tmem;
    asm volatile("ld.shared.b32 %0, [%1];" : "=r"(tmem) : "r"(sb));

    const uint32_t IDESC = (1u << 4) | (1u << 7) | (1u << 10) | (8u << 17) | (8u << 24);
    const int NC = K >> 6;
    int ph0 = 0, ph1 = 0;

    for (int kc = 0; kc < NC; ++kc) {
        const int b = kc & 1;
        if (kc >= 2) {
            if (b == 0) { MBAR_WAIT(BAR0, ph0); ph0 ^= 1; }
            else        { MBAR_WAIT(BAR1, ph1); ph1 ^= 1; }
        }
        char* Ah = base + 1024 + b * 49152;
        char* Al = Ah + 16384;
        char* Bh = Ah + 32768;
        char* Bl = Ah + 40960;
        const int kb = kc * 64;
#pragma unroll
        for (int rep = 0; rep < 4; ++rep) {
            int idx = rep * 256 + tid;
            int r = idx >> 3, u = idx & 7;
            size_t g = (size_t)(row0 + r) * K + kb + u * 8;
            uint32_t off = (uint32_t)(r * 128 + u * 16);
            off ^= (off >> 3) & 0x70;
            *(uint4*)(Ah + off) = *(const uint4*)(Ahi + g);
            *(uint4*)(Al + off) = *(const uint4*)(Alo + g);
        }
#pragma unroll
        for (int rep = 0; rep < 2; ++rep) {
            int idx = rep * 256 + tid;
            int r = idx >> 3, u = idx & 7;
            size_t g = (size_t)(col0 + r) * K + kb + u * 8;
            uint32_t off = (uint32_t)(r * 128 + u * 16);
            off ^= (off >> 3) & 0x70;
            *(uint4*)(Bh + off) = *(const uint4*)(Bhi + g);
            *(uint4*)(Bl + off) = *(const uint4*)(Blo + g);
        }
        __syncthreads();
        if (wid == 0) {
            asm volatile("fence.proxy.async.shared::cta;" ::: "memory");
            if (elect1()) {
                uint32_t abase = sb + 1024 + b * 49152;
                uint64_t adh = sdesc(abase);
                uint64_t adl = adh + (16384 >> 4);
                uint64_t bdh = adh + (32768 >> 4);
                uint64_t bdl = adh + (40960 >> 4);
#pragma unroll
                for (int ks = 0; ks < 4; ++ks) {
                    uint64_t o = (uint64_t)(ks * 2);
                    uint32_t e0 = (kc | ks) ? 1u : 0u;
                    mma_f16_ss(tmem, adh + o, bdh + o, IDESC, e0);
                    mma_f16_ss(tmem, adh + o, bdl + o, IDESC, 1u);
                    mma_f16_ss(tmem, adl + o, bdh + o, IDESC, 1u);
                }
                TCG_COMMIT(b ? BAR1 : BAR0);
            }
        }
    }
    MBAR_WAIT(BAR0, ph0);
    MBAR_WAIT(BAR1, ph1);
    TCG_FENCE_AFTER();

    if (wid < 4) {
        uint32_t d[64];
        TCG_LD32(d, tmem);
        TCG_LD32(d + 32, tmem + 32);
        TCG_WAIT_LD();
        int row = row0 + wid * 32 + lane;
        float* cp = C + (size_t)row * N + col0;
        if (EPI == 1) {
#pragma unroll
            for (int c4 = 0; c4 < 16; ++c4) {
                float4 bb = *(const float4*)(bias + col0 + c4 * 4);
                float4 v;
                v.x = sigf(__uint_as_float(d[c4 * 4 + 0]) + bb.x);
                v.y = sigf(__uint_as_float(d[c4 * 4 + 1]) + bb.y);
                v.z = sigf(__uint_as_float(d[c4 * 4 + 2]) + bb.z);
                v.w = sigf(__uint_as_float(d[c4 * 4 + 3]) + bb.w);
                *(float4*)(cp + c4 * 4) = v;
            }
        } else {
            int srow = row / O;
            const float* hp = Hs + (size_t)srow * N + col0;
#pragma unroll
            for (int c4 = 0; c4 < 16; ++c4) {
                float4 h = *(const float4*)(hp + c4 * 4);
                float4 v;
                v.x = __uint_as_float(d[c4 * 4 + 0]) * h.x * (1.0f - h.x);
                v.y = __uint_as_float(d[c4 * 4 + 1]) * h.y * (1.0f - h.y);
                v.z = __uint_as_float(d[c4 * 4 + 2]) * h.z * (1.0f - h.z);
                v.w = __uint_as_float(d[c4 * 4 + 3]) * h.w * (1.0f - h.w);
                *(float4*)(cp + c4 * 4) = v;
            }
        }
    }
    __syncthreads();
    if (wid == 0) TCG_DEALLOC(tmem, 128);
#else
    // ---------------- SIMT fallback: fp32 register-tiled 128x64 GEMM on (hi+lo) --------
    extern __shared__ char dsm[];
    float* As = (float*)dsm;          // [32][128]
    float* Bs = As + 32 * 128;        // [32][64]

    const int tid = threadIdx.x;
    const int tx = tid & 15;
    const int ty = tid >> 4;
    const int row0 = blockIdx.y * 128;
    const int col0 = blockIdx.x * 64;

    float acc[8][4];
#pragma unroll
    for (int i = 0; i < 8; ++i)
#pragma unroll
        for (int j = 0; j < 4; ++j) acc[i][j] = 0.0f;

    for (int kb = 0; kb < K; kb += 32) {
        __syncthreads();
#pragma unroll
        for (int v = 0; v < 2; ++v) {
            int i = tid * 2 + v;
            int r = i >> 2, u = (i & 3) * 8;
            size_t ga = (size_t)(row0 + r) * K + kb + u;
            uint4 h4 = *(const uint4*)(Ahi + ga);
            uint4 l4 = *(const uint4*)(Alo + ga);
            float f[8];
            cvt2(h4.x, l4.x, f[0], f[1]); cvt2(h4.y, l4.y, f[2], f[3]);
            cvt2(h4.z, l4.z, f[4], f[5]); cvt2(h4.w, l4.w, f[6], f[7]);
#pragma unroll
            for (int e = 0; e < 8; ++e) As[(u + e) * 128 + r] = f[e];
        }
        {
            int r = tid >> 2, u = (tid & 3) * 8;
            size_t gb = (size_t)(col0 + r) * K + kb + u;
            uint4 h4 = *(const uint4*)(Bhi + gb);
            uint4 l4 = *(const uint4*)(Blo + gb);
            float f[8];
            cvt2(h4.x, l4.x, f[0], f[1]); cvt2(h4.y, l4.y, f[2], f[3]);
            cvt2(h4.z, l4.z, f[4], f[5]); cvt2(h4.w, l4.w, f[6], f[7]);
#pragma unroll
            for (int e = 0; e < 8; ++e) Bs[(u + e) * 64 + r] = f[e];
        }
        __syncthreads();
#pragma unroll
        for (int k = 0; k < 32; ++k) {
            float a[8], b[4];
            *(float4*)(a + 0) = *(const float4*)&As[k * 128 + ty * 8];
            *(float4*)(a + 4) = *(const float4*)&As[k * 128 + ty * 8 + 4];
            *(float4*)(b + 0) = *(const float4*)&Bs[k * 64 + tx * 4];
#pragma unroll
            for (int i = 0; i < 8; ++i)
#pragma unroll
                for (int j = 0; j < 4; ++j) acc[i][j] += a[i] * b[j];
        }
    }

    const int r0 = row0 + ty * 8;
    const int c0 = col0 + tx * 4;
    if (EPI == 1) {
        float4 bb = *(const float4*)(bias + c0);
#pragma unroll
        for (int i = 0; i < 8; ++i) {
            float4 v;
            v.x = sigf(acc[i][0] + bb.x);
            v.y = sigf(acc[i][1] + bb.y);
            v.z = sigf(acc[i][2] + bb.z);
            v.w = sigf(acc[i][3] + bb.w);
            *(float4*)(C + (size_t)(r0 + i) * N + c0) = v;
        }
    } else {
#pragma unroll
        for (int i = 0; i < 8; ++i) {
            int srow = (r0 + i) / O;
            float4 h = *(const float4*)(Hs + (size_t)srow * N + c0);
            float4 v;
            v.x = acc[i][0] * h.x * (1.0f - h.x);
            v.y = acc[i][1] * h.y * (1.0f - h.y);
            v.z = acc[i][2] * h.z * (1.0f - h.z);
            v.w = acc[i][3] * h.w * (1.0f - h.w);
            *(float4*)(C + (size_t)(r0 + i) * N + c0) = v;
        }
    }
#endif
}

// ---------------- seed kernel: output-layer dots + backward seeds (vectorized) ----------
__global__ __launch_bounds__(128) void seed_kernel(
    const float* __restrict__ W2p, const float* __restrict__ b2p,
    const float* __restrict__ W2r0, const float* __restrict__ b2r0,
    const float* __restrict__ W2r1, const float* __restrict__ b2r1,
    const float* __restrict__ W2r2, const float* __restrict__ b2r2,
    int m) {
    const int lane = threadIdx.x & 31;
    const int s = blockIdx.x * 4 + (threadIdx.x >> 5);

    {
        const float* h2 = g_H2p + (size_t)s * 512;
        __nv_bfloat16* aph = g_Aph + (size_t)s * 1536;
        __nv_bfloat16* apl = g_Apl + (size_t)s * 1536;
        float a0 = 0.f, a1 = 0.f, a2 = 0.f;
#pragma unroll
        for (int i0 = lane * 4; i0 < 512; i0 += 128) {
            float4 h4 = *(const float4*)(h2 + i0);
            float4 w0 = *(const float4*)(W2p + i0 * 3);
            float4 w1 = *(const float4*)(W2p + i0 * 3 + 4);
            float4 w2 = *(const float4*)(W2p + i0 * 3 + 8);
            float hv[4] = {h4.x, h4.y, h4.z, h4.w};
            float wv[12] = {w0.x, w0.y, w0.z, w0.w, w1.x, w1.y,
                            w1.z, w1.w, w2.x, w2.y, w2.z, w2.w};
            __nv_bfloat16 oh[3][4], ol[3][4];
#pragma unroll
            for (int e = 0; e < 4; ++e) {
                float h = hv[e], d = h * (1.0f - h);
                float wa = wv[e * 3], wb = wv[e * 3 + 1], wc = wv[e * 3 + 2];
                a0 += h * wa; a1 += h * wb; a2 += h * wc;
                split_bf16(d * wa, oh[0][e], ol[0][e]);
                split_bf16(d * wb, oh[1][e], ol[1][e]);
                split_bf16(d * wc, oh[2][e], ol[2][e]);
            }
#pragma unroll
            for (int o = 0; o < 3; ++o) {
                uint2 uh, ul;
                uh.x = pack_bf(oh[o][0], oh[o][1]); uh.y = pack_bf(oh[o][2], oh[o][3]);
                ul.x = pack_bf(ol[o][0], ol[o][1]); ul.y = pack_bf(ol[o][2], ol[o][3]);
                *(uint2*)(aph + o * 512 + i0) = uh;
                *(uint2*)(apl + o * 512 + i0) = ul;
            }
        }
        a0 = wred(a0); a1 = wred(a1); a2 = wred(a2);
        if (lane == 0) {
            g_aux[s * 9 + 0] = a0 + b2p[0];
            g_aux[s * 9 + 1] = a1 + b2p[1];
            g_aux[s * 9 + 2] = a2 + b2p[2];
        }
    }
    const float* W2h[3] = {W2r0, W2r1, W2r2};
    const float* b2h[3] = {b2r0, b2r1, b2r2};
#pragma unroll
    for (int t = 0; t < 3; ++t) {
        const float* h2 = g_H2r + ((size_t)t * m + s) * 256;
        __nv_bfloat16* arh = g_Arh + ((size_t)t * m + s) * 512;
        __nv_bfloat16* arl = g_Arl + ((size_t)t * m + s) * 512;
        const float* W = W2h[t];
        float a0 = 0.f, a1 = 0.f;
#pragma unroll
        for (int i0 = lane * 4; i0 < 256; i0 += 128) {
            float4 h4 = *(const float4*)(h2 + i0);
            float4 w0 = *(const float4*)(W + i0 * 2);
            float4 w1 = *(const float4*)(W + i0 * 2 + 4);
            float hv[4] = {h4.x, h4.y, h4.z, h4.w};
            float wv[8] = {w0.x, w0.y, w0.z, w0.w, w1.x, w1.y, w1.z, w1.w};
            __nv_bfloat16 oh[2][4], ol[2][4];
#pragma unroll
            for (int e = 0; e < 4; ++e) {
                float h = hv[e], d = h * (1.0f - h);
                float wa = wv[e * 2], wb = wv[e * 2 + 1];
                a0 += h * wa; a1 += h * wb;
                split_bf16(d * wa, oh[0][e], ol[0][e]);
                split_bf16(d * wb, oh[1][e], ol[1][e]);
            }
#pragma unroll
            for (int o = 0; o < 2; ++o) {
                uint2 uh, ul;
                uh.x = pack_bf(oh[o][0], oh[o][1]); uh.y = pack_bf(oh[o][2], oh[o][3]);
                ul.x = pack_bf(ol[o][0], ol[o][1]); ul.y = pack_bf(ol[o][2], ol[o][3]);
                *(uint2*)(arh + o * 256 + i0) = uh;
                *(uint2*)(arl + o * 256 + i0) = ul;
            }
        }
        a0 = wred(a0); a1 = wred(a1);
        if (lane == 0) {
            g_aux[s * 9 + 3 + 2 * t] = a0 + b2h[t][0];
            g_aux[s * 9 + 4 + 2 * t] = a1 + b2h[t][1];
        }
    }
}

// ---------------- final kernel: J projection to inputs, chain rule, assembly ----------------
__global__ __launch_bounds__(128) void final_kernel(
    const float* __restrict__ x,
    const float* __restrict__ W0p,
    const float* __restrict__ W0r0, const float* __restrict__ W0r1, const float* __restrict__ W0r2,
    float* __restrict__ out, int m) {
    __shared__ float sWp[7 * 512];
    __shared__ float sWr[3][7 * 256];
    for (int i = threadIdx.x; i < 7 * 512; i += 128) sWp[i] = W0p[i];
    for (int i = threadIdx.x; i < 7 * 256; i += 128) {
        sWr[0][i] = W0r0[i]; sWr[1][i] = W0r1[i]; sWr[2][i] = W0r2[i];
    }
    __syncthreads();

    const int lane = threadIdx.x & 31;
    const int s = blockIdx.x * 4 + (threadIdx.x >> 5);

    float accP[21];
#pragma unroll
    for (int p = 0; p < 21; ++p) accP[p] = 0.0f;
    {
        const float* g = g_G1p + (size_t)s * 1536;
        for (int i = lane; i < 512; i += 32) {
            float g0 = g[i], g1 = g[512 + i], g2 = g[1024 + i];
#pragma unroll
            for (int j = 0; j < 7; ++j) {
                float w = sWp[j * 512 + i];
                accP[j]      += g0 * w;
                accP[7 + j]  += g1 * w;
                accP[14 + j] += g2 * w;
            }
        }
    }
    float accH[42];
#pragma unroll
    for (int p = 0; p < 42; ++p) accH[p] = 0.0f;
#pragma unroll
    for (int t = 0; t < 3; ++t) {
        const float* gr = g_G1r + ((size_t)t * m + s) * 512;
        for (int i = lane; i < 256; i += 32) {
            float g0 = gr[i], g1 = gr[256 + i];
#pragma unroll
            for (int j = 0; j < 7; ++j) {
                float w = sWr[t][j * 256 + i];
                accH[t * 14 + j]     += g0 * w;
                accH[t * 14 + 7 + j] += g1 * w;
            }
        }
    }
#pragma unroll
    for (int p = 0; p < 21; ++p) accP[p] = wred(accP[p]);
#pragma unroll
    for (int p = 0; p < 42; ++p) accH[p] = wred(accH[p]);

    if (lane == 0) {
        float qd[7];
#pragma unroll
        for (int j = 0; j < 7; ++j) qd[j] = x[(size_t)s * 14 + 7 + j];
        float P0 = g_aux[s * 9 + 0], P1 = g_aux[s * 9 + 1], P2 = g_aux[s * 9 + 2];

        float sn[3], cs[3], ang[3];
        float R0[3][7], R1[3][7], R2[3][7];
#pragma unroll
        for (int t = 0; t < 3; ++t) {
            float y0 = g_aux[s * 9 + 3 + 2 * t];
            float y1 = g_aux[s * 9 + 4 + 2 * t];
            float s_ = sinf(y0), cy0 = cosf(y0);
            float c_ = cosf(y1), sy1 = sinf(y1);
            sn[t] = s_; cs[t] = c_;
            ang[t] = atan2f(s_, c_);
            float inv = 1.0f / (s_ * s_ + c_ * c_);
#pragma unroll
            for (int j = 0; j < 7; ++j) {
                float j0 = accH[t * 14 + j], j1 = accH[t * 14 + 7 + j];
                R0[t][j] = cy0 * j0;
                R1[t][j] = -sy1 * j1;
                R2[t][j] = inv * (c_ * cy0 * j0 + s_ * sy1 * j1);
            }
        }
        float velP[3], v0[3], v1[3];
#pragma unroll
        for (int o = 0; o < 3; ++o) {
            float a = 0.f;
#pragma unroll
            for (int j = 0; j < 7; ++j) a += accP[o * 7 + j] * qd[j];
            velP[o] = a;
        }
#pragma unroll
        for (int t = 0; t < 3; ++t) {
            float a = 0.f, b = 0.f;
#pragma unroll
            for (int j = 0; j < 7; ++j) { a += R0[t][j] * qd[j]; b += R1[t][j] * qd[j]; }
            v0[t] = a; v1[t] = b;
        }

        float* o1 = out + (size_t)s * 18;
        o1[0] = P0; o1[1] = P1; o1[2] = P2;
#pragma unroll
        for (int t = 0; t < 3; ++t) {
            o1[3 + t] = sn[t]; o1[6 + t] = cs[t];
            o1[12 + t] = v0[t]; o1[15 + t] = v1[t];
        }
#pragma unroll
        for (int o = 0; o < 3; ++o) o1[9 + o] = velP[o];

        float* J = out + (size_t)m * 18 + (size_t)s * 63;
#pragma unroll
        for (int p = 0; p < 21; ++p) J[p] = accP[p];
#pragma unroll
        for (int t = 0; t < 3; ++t)
#pragma unroll
            for (int j = 0; j < 7; ++j) {
                J[(3 + t) * 7 + j] = R0[t][j];
                J[(6 + t) * 7 + j] = R1[t][j];
            }

        float* oa = out + (size_t)m * 81 + (size_t)s * 6;
        oa[0] = P0; oa[1] = P1; oa[2] = P2;
#pragma unroll
        for (int t = 0; t < 3; ++t) oa[3 + t] = ang[t];

        float* Ja = out + (size_t)m * 87 + (size_t)s * 42;
#pragma unroll
        for (int p = 0; p < 21; ++p) Ja[p] = accP[p];
#pragma unroll
        for (int t = 0; t < 3; ++t)
#pragma unroll
            for (int j = 0; j < 7; ++j) Ja[(3 + t) * 7 + j] = R2[t][j];
    }
}

// ---------------- launch ----------------
extern "C" void kernel_launch(void* const* d_in, const int* in_sizes, int n_in,
                              void* d_out, int out_size) {
    const float* x   = (const float*)d_in[0];
    const float* pW0 = (const float*)d_in[1];
    const float* pb0 = (const float*)d_in[2];
    const float* pW1 = (const float*)d_in[3];
    const float* pb1 = (const float*)d_in[4];
    const float* pW2 = (const float*)d_in[5];
    const float* pb2 = (const float*)d_in[6];
    const float* hW0[3]; const float* hb0[3];
    const float* hW1[3]; const float* hb1[3];
    const float* hW2[3]; const float* hb2[3];
    for (int t = 0; t < 3; ++t) {
        int base = 7 + t * 6;
        hW0[t] = (const float*)d_in[base + 0];
        hb0[t] = (const float*)d_in[base + 1];
        hW1[t] = (const float*)d_in[base + 2];
        hb1[t] = (const float*)d_in[base + 3];
        hW2[t] = (const float*)d_in[base + 4];
        hb2[t] = (const float*)d_in[base + 5];
    }
    const int m = in_sizes[0] / 14;  // 16384
    float* out = (float*)d_out;
    (void)n_in; (void)out_size;

    float *H1p, *G1p;
    __nv_bfloat16 *H1ph, *H1pl, *H1rh, *H1rl, *Aph, *Apl, *Arh, *Arl;
    float *H1r, *H2p, *H2r, *G1r;
    __nv_bfloat16 *W1dh, *W1dl, *W1th, *W1tl, *Wrdh, *Wrdl, *Wrth, *Wrtl;
    cudaGetSymbolAddress((void**)&H1p,  g_H1p);
    cudaGetSymbolAddress((void**)&H2p,  g_H2p);
    cudaGetSymbolAddress((void**)&H1r,  g_H1r);
    cudaGetSymbolAddress((void**)&H2r,  g_H2r);
    cudaGetSymbolAddress((void**)&G1p,  g_G1p);
    cudaGetSymbolAddress((void**)&G1r,  g_G1r);
    cudaGetSymbolAddress((void**)&H1ph, g_H1ph);
    cudaGetSymbolAddress((void**)&H1pl, g_H1pl);
    cudaGetSymbolAddress((void**)&H1rh, g_H1rh);
    cudaGetSymbolAddress((void**)&H1rl, g_H1rl);
    cudaGetSymbolAddress((void**)&Aph,  g_Aph);
    cudaGetSymbolAddress((void**)&Apl,  g_Apl);
    cudaGetSymbolAddress((void**)&Arh,  g_Arh);
    cudaGetSymbolAddress((void**)&Arl,  g_Arl);
    cudaGetSymbolAddress((void**)&W1dh, g_W1d_h);
    cudaGetSymbolAddress((void**)&W1dl, g_W1d_l);
    cudaGetSymbolAddress((void**)&W1th, g_W1t_h);
    cudaGetSymbolAddress((void**)&W1tl, g_W1t_l);
    cudaGetSymbolAddress((void**)&Wrdh, g_Wrd_h);
    cudaGetSymbolAddress((void**)&Wrdl, g_Wrd_l);
    cudaGetSymbolAddress((void**)&Wrth, g_Wrt_h);
    cudaGetSymbolAddress((void**)&Wrtl, g_Wrt_l);

    cudaFuncSetAttribute(tc_gemm<1>, cudaFuncAttributeMaxDynamicSharedMemorySize, TCG_SMEM_BYTES);
    cudaFuncSetAttribute(tc_gemm<2>, cudaFuncAttributeMaxDynamicSharedMemorySize, TCG_SMEM_BYTES);

    // weight prep: bf16 hi/lo, direct ([j][i]) and transposed ([n][k]) layouts
    wprep_kernel<<<(512 * 512 + 255) / 256, 256>>>(pW1, 512, W1dh, W1dl, W1th, W1tl);
    wpreph_kernel<<<dim3((256 * 256) / 256, 1, 3), 256>>>(
        hW1[0], hW1[1], hW1[2], Wrdh, Wrdl, Wrth, Wrtl);

    // fused layer-1 forward (all 4 networks, 8 samples/block)
    fwd1all_kernel<<<dim3(m / 8, 5), 256>>>(x, pW0, pb0, hW0[0], hW0[1], hW0[2],
                                            hb0[0], hb0[1], hb0[2], m);

    // layer-2 forward GEMMs (sigmoid epilogue), 128x64 tiles
    tc_gemm<1><<<dim3(8, m / 128, 1), 256, TCG_SMEM_BYTES>>>(
        512, 512, H1ph, H1pl, 0, W1th, W1tl, 0, pb1, pb1, pb1, nullptr, 0, 1, H2p, 0);
    tc_gemm<1><<<dim3(4, m / 128, 3), 256, TCG_SMEM_BYTES>>>(
        256, 256, H1rh, H1rl, (size_t)m * 256, Wrth, Wrtl, 65536,
        hb1[0], hb1[1], hb1[2], nullptr, 0, 1, H2r, (size_t)m * 256);

    // output-layer dots + backward seeds (bf16 hi/lo, vectorized)
    seed_kernel<<<m / 4, 128>>>(pW2, pb2, hW2[0], hb2[0], hW2[1], hb2[1], hW2[2], hb2[2], m);

    // backward GEMMs (dsigmoid epilogue): G1 = (A @ W1^T) .* sigma1'
    tc_gemm<2><<<dim3(8, (3 * m) / 128, 1), 256, TCG_SMEM_BYTES>>>(
        512, 512, Aph, Apl, 0, W1dh, W1dl, 0, nullptr, nullptr, nullptr,
        H1p, 0, 3, G1p, 0);
    tc_gemm<2><<<dim3(4, (2 * m) / 128, 3), 256, TCG_SMEM_BYTES>>>(
        256, 256, Arh, Arl, (size_t)m * 512, Wrdh, Wrdl, 65536,
        nullptr, nullptr, nullptr, H1r, (size_t)m * 256, 2, G1r, (size_t)m * 512);

    // input-side projection + trig chain rule + output assembly
    final_kernel<<<m / 4, 128>>>(x, pW0, hW0[0], hW0[1], hW0[2], out, m);
}